// round 2
// baseline (speedup 1.0000x reference)
#include <cuda_runtime.h>

#define PL (512*512)
typedef unsigned long long u64;

// ---------------- scratch ----------------
__device__ float g_t[8][4][16][2];
__device__ float g_scal[3];
__device__ float g_part[8][512][2];
__device__ float g_stats[8][2];
__device__ float g_mi[8][2][16][512];
__device__ float g_mj[8][2][16][512];
__device__ float g_mod[8][2][PL];
__device__ float g_wd0[8][2][PL];
__device__ float g_P[8][2][PL];
__device__ float g_Wi[2][PL];
__device__ float g_Wj[2][PL];

// ---------------- f32x2 helpers ----------------
__device__ __forceinline__ u64 fma2(u64 a, u64 b, u64 c) {
    u64 d; asm("fma.rn.f32x2 %0, %1, %2, %3;" : "=l"(d) : "l"(a), "l"(b), "l"(c));
    return d;
}
__device__ __forceinline__ u64 neg2(u64 a) { return a ^ 0x8000000080000000ULL; }
__device__ __forceinline__ void unpack2(u64 v, float& lo, float& hi) {
    asm("mov.b64 {%0, %1}, %2;" : "=f"(lo), "=f"(hi) : "l"(v));
}

// ---------------- k_setup ----------------
__global__ void k_setup(const float* __restrict__ x, const float* __restrict__ mt,
                        const float* __restrict__ td, const float* __restrict__ rd) {
    int tid = threadIdx.x;
    for (int o = tid; o < 1024; o += 256) {
        int e = o & 1, c2 = (o >> 1) & 15, k = (o >> 5) & 3, b = o >> 7;
        float s = 0.f;
        #pragma unroll
        for (int c = 0; c < 16; ++c)
            s += x[b * 16 + c] * mt[(k * 16 + c) * 32 + c2 * 2 + e];
        g_t[b][k][c2][e] = s;
    }
    if (tid == 0) {
        float A = 0.f, Bv = 0.f, K = 0.f;
        for (int c = 0; c < 16; ++c) {
            float rr = rd[2 * c], ri = rd[2 * c + 1];
            float tr = td[2 * c], ti = td[2 * c + 1];
            A += ri; Bv -= rr; K += ti * ri - tr * rr;
        }
        g_scal[0] = A; g_scal[1] = Bv; g_scal[2] = K;
    }
}

// ---------------- k_mimj ----------------
__global__ void k_mimj(const float* __restrict__ mod_i, const float* __restrict__ mod_j,
                       const float* __restrict__ inv) {
    int b = blockIdx.x >> 4, r = blockIdx.x & 15, m = threadIdx.x;
    __shared__ float st[16][8];
    __shared__ float siv[16][2];
    if (m < 128) st[m >> 3][m & 7] = g_t[b][(m & 7) >> 1][m >> 3][m & 1];
    if (m < 32)  siv[m >> 1][m & 1] = inv[m];
    __syncthreads();

    float sir = 0.f, sii = 0.f, sjr = 0.f, sji = 0.f;
    #pragma unroll 4
    for (int c = 0; c < 16; ++c) {
        float t0r = st[c][0], t0i = st[c][1], t1r = st[c][2], t1i = st[c][3];
        float t2r = st[c][4], t2i = st[c][5], t3r = st[c][6], t3i = st[c][7];
        float ivr = siv[c][0], ivi = siv[c][1];
        float2 vi = ((const float2*)mod_i)[(c * 16 + r) * 512 + m];
        float ar = vi.x + t0r, ai = vi.y + t0i;
        float r1 = ai * t1i - ar * t1r;
        float i1 = ar * t1i + ai * t1r;
        sir += i1 * ivi - r1 * ivr;
        sii += r1 * ivi + i1 * ivr;
        float2 vj = ((const float2*)mod_j)[(c * 16 + r) * 512 + m];
        float br2 = vj.x + t2r, bi2 = vj.y + t2i;
        float r2 = bi2 * t3i - br2 * t3r;
        float i2 = br2 * t3i + bi2 * t3r;
        float idn = 1.f / (r2 * r2 + i2 * i2);
        sjr += (ivr * r2 + ivi * i2) * idn;
        sji += (ivr * i2 - ivi * r2) * idn;
    }
    g_mi[b][0][r][m] = sir; g_mi[b][1][r][m] = sii;
    g_mj[b][0][r][m] = sjr; g_mj[b][1][r][m] = sji;
}

// ---------------- k_mod ----------------
__global__ void k_mod() {
    int b = blockIdx.x >> 9, m = blockIdx.x & 511;
    int tid = threadIdx.x;
    __shared__ float smi[2][16];
    if (tid < 32) smi[tid >> 4][tid & 15] = g_mi[b][tid >> 4][tid & 15][m];
    __syncthreads();
    float s1 = 0.f, s2 = 0.f;
    #pragma unroll
    for (int q = 0; q < 4; ++q) {
        int n = tid + q * 128;
        float cr = 0.f, ci = 0.f;
        #pragma unroll
        for (int r = 0; r < 16; ++r) {
            float air = smi[0][r], aii = smi[1][r];
            float bjr = g_mj[b][0][r][n], bji = g_mj[b][1][r][n];
            cr += air * bjr - aii * bji;
            ci += air * bji + aii * bjr;
        }
        g_mod[b][0][m * 512 + n] = cr;
        g_mod[b][1][m * 512 + n] = ci;
        s1 += cr; s2 += cr * cr;
    }
    __shared__ float rs1[128], rs2[128];
    rs1[tid] = s1; rs2[tid] = s2; __syncthreads();
    for (int off = 64; off; off >>= 1) {
        if (tid < off) { rs1[tid] += rs1[tid + off]; rs2[tid] += rs2[tid + off]; }
        __syncthreads();
    }
    if (tid == 0) { g_part[b][m][0] = rs1[0]; g_part[b][m][1] = rs2[0]; }
}

// ---------------- k_stats ----------------
__global__ void k_stats() {
    int b = blockIdx.x, t = threadIdx.x;
    __shared__ float r1[256], r2[256];
    r1[t] = g_part[b][t][0] + g_part[b][t + 256][0];
    r2[t] = g_part[b][t][1] + g_part[b][t + 256][1];
    __syncthreads();
    for (int off = 128; off; off >>= 1) {
        if (t < off) { r1[t] += r1[t + off]; r2[t] += r2[t + off]; }
        __syncthreads();
    }
    if (t == 0) { g_stats[b][0] = r1[0]; g_stats[b][1] = r2[0]; }
}

// ---------------- k_deint ----------------
__global__ void k_deint(const float* __restrict__ Wi, const float* __restrict__ Wj) {
    int vid = blockIdx.x * 256 + threadIdx.x;
    float4 a = ((const float4*)Wi)[vid];
    int p = vid * 2;
    g_Wi[0][p] = a.x; g_Wi[1][p] = a.y; g_Wi[0][p + 1] = a.z; g_Wi[1][p + 1] = a.w;
    float4 c = ((const float4*)Wj)[vid];
    g_Wj[0][p] = c.x; g_Wj[1][p] = c.y; g_Wj[0][p + 1] = c.z; g_Wj[1][p + 1] = c.w;
}

// ---------------- k_wd0 ----------------
__global__ void k_wd0(const float* __restrict__ wb) {
    int b = blockIdx.x >> 8;
    int seg = blockIdx.x & 255;
    int p = seg * 1024 + threadIdx.x * 4;
    float s1 = g_stats[b][0], s2 = g_stats[b][1];
    float mean = s1 * (1.f / 262144.f);
    float var = (s2 - s1 * mean) * (1.f / 262143.f);
    float istd = rsqrtf(var);
    float4 mr = *(const float4*)&g_mod[b][0][p];
    float4 mi = *(const float4*)&g_mod[b][1][p];
    float4 w01 = *(const float4*)&wb[2 * p];
    float4 w23 = *(const float4*)&wb[2 * p + 4];
    float4 orr = make_float4(
        w01.x * (1.f + (mr.x - mean) * istd),
        w01.z * (1.f + (mr.y - mean) * istd),
        w23.x * (1.f + (mr.z - mean) * istd),
        w23.z * (1.f + (mr.w - mean) * istd));
    float4 oii = make_float4(
        w01.y * (1.f + mi.x), w01.w * (1.f + mi.y),
        w23.y * (1.f + mi.z), w23.w * (1.f + mi.w));
    *(float4*)&g_wd0[b][0][p] = orr;
    *(float4*)&g_wd0[b][1][p] = oii;
}

// ---------------- complex GEMM via packed FFMA2 ----------------
// C[i,j] = sum_k A[k,i]*B[k,j] (complex). Accumulators packed along i-pairs.
// B staged into smem DUPLICATED (each scalar twice) so packed splats come
// straight from LDS.128 with zero pack-MOVs.
template<int STAGE>
__global__ __launch_bounds__(256, 2) void k_cgemm(float* __restrict__ gout) {
    constexpr int BI = 128, BJ = 64, BK = 16;
    const int b = blockIdx.z;
    const float* __restrict__ Ar; const float* __restrict__ Ai;
    const float* __restrict__ Br; const float* __restrict__ Bi;
    if (STAGE == 0) { Ar = g_Wi[0];   Ai = g_Wi[1];   Br = g_wd0[b][0]; Bi = g_wd0[b][1]; }
    else            { Ar = g_P[b][0]; Ai = g_P[b][1]; Br = g_Wj[0];     Bi = g_Wj[1]; }

    const int i0 = blockIdx.y * BI, j0 = blockIdx.x * BJ;
    __shared__ __align__(16) float Asr[BK][BI], Asi[BK][BI];
    __shared__ __align__(16) float Bsr2[BK][BJ * 2], Bsi2[BK][BJ * 2];

    u64 crp[4][4], cip[4][4];
    #pragma unroll
    for (int up = 0; up < 4; ++up)
        #pragma unroll
        for (int v = 0; v < 4; ++v) { crp[up][v] = 0ULL; cip[up][v] = 0ULL; }

    const int tid = threadIdx.x, tx = tid & 15, ty = tid >> 4;
    const int a_kk = tid >> 5, a_ii = (tid & 31) * 4;
    const int b_kk = tid >> 4, b_jj = (tid & 15) * 4;

    for (int k0 = 0; k0 < 512; k0 += BK) {
        #pragma unroll
        for (int h = 0; h < 2; ++h) {
            int kk = a_kk + h * 8;
            *(float4*)&Asr[kk][a_ii] = *(const float4*)&Ar[(k0 + kk) * 512 + i0 + a_ii];
            *(float4*)&Asi[kk][a_ii] = *(const float4*)&Ai[(k0 + kk) * 512 + i0 + a_ii];
        }
        {
            float4 vr = *(const float4*)&Br[(k0 + b_kk) * 512 + j0 + b_jj];
            float4 vi = *(const float4*)&Bi[(k0 + b_kk) * 512 + j0 + b_jj];
            *(float4*)&Bsr2[b_kk][b_jj * 2]     = make_float4(vr.x, vr.x, vr.y, vr.y);
            *(float4*)&Bsr2[b_kk][b_jj * 2 + 4] = make_float4(vr.z, vr.z, vr.w, vr.w);
            *(float4*)&Bsi2[b_kk][b_jj * 2]     = make_float4(vi.x, vi.x, vi.y, vi.y);
            *(float4*)&Bsi2[b_kk][b_jj * 2 + 4] = make_float4(vi.z, vi.z, vi.w, vi.w);
        }
        __syncthreads();
        #pragma unroll 8
        for (int kk = 0; kk < BK; ++kk) {
            // A fragments: packed i-pairs, straight from LDS.128
            ulonglong2 ar01 = *(const ulonglong2*)&Asr[kk][ty * 8];
            ulonglong2 ar23 = *(const ulonglong2*)&Asr[kk][ty * 8 + 4];
            ulonglong2 ai01 = *(const ulonglong2*)&Asi[kk][ty * 8];
            ulonglong2 ai23 = *(const ulonglong2*)&Asi[kk][ty * 8 + 4];
            u64 arp[4] = { ar01.x, ar01.y, ar23.x, ar23.y };
            u64 aip[4] = { ai01.x, ai01.y, ai23.x, ai23.y };
            u64 ainp[4] = { neg2(aip[0]), neg2(aip[1]), neg2(aip[2]), neg2(aip[3]) };
            // B fragments: packed splats, straight from duplicated smem
            ulonglong2 br01 = *(const ulonglong2*)&Bsr2[kk][tx * 8];
            ulonglong2 br23 = *(const ulonglong2*)&Bsr2[kk][tx * 8 + 4];
            ulonglong2 bi01 = *(const ulonglong2*)&Bsi2[kk][tx * 8];
            ulonglong2 bi23 = *(const ulonglong2*)&Bsi2[kk][tx * 8 + 4];
            u64 br2[4] = { br01.x, br01.y, br23.x, br23.y };
            u64 bi2[4] = { bi01.x, bi01.y, bi23.x, bi23.y };
            #pragma unroll
            for (int up = 0; up < 4; ++up)
                #pragma unroll
                for (int v = 0; v < 4; ++v) {
                    crp[up][v] = fma2(arp[up],  br2[v], crp[up][v]);
                    crp[up][v] = fma2(ainp[up], bi2[v], crp[up][v]);
                    cip[up][v] = fma2(arp[up],  bi2[v], cip[up][v]);
                    cip[up][v] = fma2(aip[up],  br2[v], cip[up][v]);
                }
        }
        __syncthreads();
    }

    // unpack to scalar microtile
    float cr[8][4], ci[8][4];
    #pragma unroll
    for (int up = 0; up < 4; ++up)
        #pragma unroll
        for (int v = 0; v < 4; ++v) {
            unpack2(crp[up][v], cr[2 * up][v], cr[2 * up + 1][v]);
            unpack2(cip[up][v], ci[2 * up][v], ci[2 * up + 1][v]);
        }

    if (STAGE == 0) {
        float* Pr = g_P[b][0]; float* Pi = g_P[b][1];
        #pragma unroll
        for (int v = 0; v < 4; ++v) {
            int j = j0 + tx * 4 + v;
            int base = j * 512 + i0 + ty * 8;
            *(float4*)&Pr[base]     = make_float4(cr[0][v], cr[1][v], cr[2][v], cr[3][v]);
            *(float4*)&Pr[base + 4] = make_float4(cr[4][v], cr[5][v], cr[6][v], cr[7][v]);
            *(float4*)&Pi[base]     = make_float4(ci[0][v], ci[1][v], ci[2][v], ci[3][v]);
            *(float4*)&Pi[base + 4] = make_float4(ci[4][v], ci[5][v], ci[6][v], ci[7][v]);
        }
    } else {
        float A_ = g_scal[0], B_ = g_scal[1], K_ = g_scal[2];
        float* O = gout + b * PL;
        #pragma unroll
        for (int u = 0; u < 8; ++u) {
            int i = i0 + ty * 8 + u;
            float4 o = make_float4(
                fmaf(ci[u][0], A_, fmaf(cr[u][0], B_, K_)),
                fmaf(ci[u][1], A_, fmaf(cr[u][1], B_, K_)),
                fmaf(ci[u][2], A_, fmaf(cr[u][2], B_, K_)),
                fmaf(ci[u][3], A_, fmaf(cr[u][3], B_, K_)));
            *(float4*)&O[i * 512 + j0 + tx * 4] = o;
        }
    }
}

// ---------------- launch ----------------
extern "C" void kernel_launch(void* const* d_in, const int* in_sizes, int n_in,
                              void* d_out, int out_size) {
    (void)in_sizes; (void)n_in; (void)out_size;
    const float* x   = (const float*)d_in[0];
    const float* Wi  = (const float*)d_in[1];
    const float* Wj  = (const float*)d_in[2];
    const float* Wb  = (const float*)d_in[3];
    const float* td  = (const float*)d_in[6];
    const float* rd  = (const float*)d_in[7];
    const float* mi  = (const float*)d_in[8];
    const float* mj  = (const float*)d_in[9];
    const float* inv = (const float*)d_in[10];
    const float* mt  = (const float*)d_in[11];
    float* out = (float*)d_out;

    k_setup<<<1, 256>>>(x, mt, td, rd);
    k_mimj<<<128, 512>>>(mi, mj, inv);
    k_mod<<<4096, 128>>>();
    k_stats<<<8, 256>>>();
    k_deint<<<512, 256>>>(Wi, Wj);
    k_wd0<<<2048, 256>>>(Wb);
    dim3 grid(8, 4, 8);
    k_cgemm<0><<<grid, 256>>>(nullptr);
    k_cgemm<1><<<grid, 256>>>(out);
}

// round 5
// speedup vs baseline: 1.0041x; 1.0041x over previous
#include <cuda_runtime.h>

#define PL (512*512)
typedef unsigned long long u64;

// ---------------- scratch ----------------
__device__ float g_t[8][4][16][2];
__device__ float g_scal[3];
__device__ float g_part[8][512][2];
__device__ float g_stats[8][2];
__device__ float g_mi[8][2][16][512];
__device__ float g_mj[8][2][16][512];
__device__ float g_mod[8][2][PL];
__device__ float g_wd0[8][2][PL];
__device__ float g_P[8][2][PL];
__device__ float g_Wi[2][PL];
__device__ float g_Wj[2][PL];

// ---------------- f32x2 helpers ----------------
__device__ __forceinline__ u64 fma2(u64 a, u64 b, u64 c) {
    u64 d; asm("fma.rn.f32x2 %0, %1, %2, %3;" : "=l"(d) : "l"(a), "l"(b), "l"(c));
    return d;
}
__device__ __forceinline__ u64 neg2(u64 a) { return a ^ 0x8000000080000000ULL; }
__device__ __forceinline__ void unpack2(u64 v, float& lo, float& hi) {
    asm("mov.b64 {%0, %1}, %2;" : "=f"(lo), "=f"(hi) : "l"(v));
}

// ---------------- k_setup ----------------
__global__ void k_setup(const float* __restrict__ x, const float* __restrict__ mt,
                        const float* __restrict__ td, const float* __restrict__ rd) {
    int tid = threadIdx.x;
    for (int o = tid; o < 1024; o += 256) {
        int e = o & 1, c2 = (o >> 1) & 15, k = (o >> 5) & 3, b = o >> 7;
        float s = 0.f;
        #pragma unroll
        for (int c = 0; c < 16; ++c)
            s += x[b * 16 + c] * mt[(k * 16 + c) * 32 + c2 * 2 + e];
        g_t[b][k][c2][e] = s;
    }
    if (tid == 0) {
        float A = 0.f, Bv = 0.f, K = 0.f;
        for (int c = 0; c < 16; ++c) {
            float rr = rd[2 * c], ri = rd[2 * c + 1];
            float tr = td[2 * c], ti = td[2 * c + 1];
            A += ri; Bv -= rr; K += ti * ri - tr * rr;
        }
        g_scal[0] = A; g_scal[1] = Bv; g_scal[2] = K;
    }
}

// ---------------- k_mimj ----------------
__global__ void k_mimj(const float* __restrict__ mod_i, const float* __restrict__ mod_j,
                       const float* __restrict__ inv) {
    int b = blockIdx.x >> 4, r = blockIdx.x & 15, m = threadIdx.x;
    __shared__ float st[16][8];
    __shared__ float siv[16][2];
    if (m < 128) st[m >> 3][m & 7] = g_t[b][(m & 7) >> 1][m >> 3][m & 1];
    if (m < 32)  siv[m >> 1][m & 1] = inv[m];
    __syncthreads();

    float sir = 0.f, sii = 0.f, sjr = 0.f, sji = 0.f;
    #pragma unroll 4
    for (int c = 0; c < 16; ++c) {
        float t0r = st[c][0], t0i = st[c][1], t1r = st[c][2], t1i = st[c][3];
        float t2r = st[c][4], t2i = st[c][5], t3r = st[c][6], t3i = st[c][7];
        float ivr = siv[c][0], ivi = siv[c][1];
        float2 vi = ((const float2*)mod_i)[(c * 16 + r) * 512 + m];
        float ar = vi.x + t0r, ai = vi.y + t0i;
        float r1 = ai * t1i - ar * t1r;
        float i1 = ar * t1i + ai * t1r;
        sir += i1 * ivi - r1 * ivr;
        sii += r1 * ivi + i1 * ivr;
        float2 vj = ((const float2*)mod_j)[(c * 16 + r) * 512 + m];
        float br2 = vj.x + t2r, bi2 = vj.y + t2i;
        float r2 = bi2 * t3i - br2 * t3r;
        float i2 = br2 * t3i + bi2 * t3r;
        float idn = 1.f / (r2 * r2 + i2 * i2);
        sjr += (ivr * r2 + ivi * i2) * idn;
        sji += (ivr * i2 - ivi * r2) * idn;
    }
    g_mi[b][0][r][m] = sir; g_mi[b][1][r][m] = sii;
    g_mj[b][0][r][m] = sjr; g_mj[b][1][r][m] = sji;
}

// ---------------- k_mod ----------------
__global__ void k_mod() {
    int b = blockIdx.x >> 9, m = blockIdx.x & 511;
    int tid = threadIdx.x;
    __shared__ float smi[2][16];
    if (tid < 32) smi[tid >> 4][tid & 15] = g_mi[b][tid >> 4][tid & 15][m];
    __syncthreads();
    float s1 = 0.f, s2 = 0.f;
    #pragma unroll
    for (int q = 0; q < 4; ++q) {
        int n = tid + q * 128;
        float cr = 0.f, ci = 0.f;
        #pragma unroll
        for (int r = 0; r < 16; ++r) {
            float air = smi[0][r], aii = smi[1][r];
            float bjr = g_mj[b][0][r][n], bji = g_mj[b][1][r][n];
            cr += air * bjr - aii * bji;
            ci += air * bji + aii * bjr;
        }
        g_mod[b][0][m * 512 + n] = cr;
        g_mod[b][1][m * 512 + n] = ci;
        s1 += cr; s2 += cr * cr;
    }
    __shared__ float rs1[128], rs2[128];
    rs1[tid] = s1; rs2[tid] = s2; __syncthreads();
    for (int off = 64; off; off >>= 1) {
        if (tid < off) { rs1[tid] += rs1[tid + off]; rs2[tid] += rs2[tid + off]; }
        __syncthreads();
    }
    if (tid == 0) { g_part[b][m][0] = rs1[0]; g_part[b][m][1] = rs2[0]; }
}

// ---------------- k_stats ----------------
__global__ void k_stats() {
    int b = blockIdx.x, t = threadIdx.x;
    __shared__ float r1[256], r2[256];
    r1[t] = g_part[b][t][0] + g_part[b][t + 256][0];
    r2[t] = g_part[b][t][1] + g_part[b][t + 256][1];
    __syncthreads();
    for (int off = 128; off; off >>= 1) {
        if (t < off) { r1[t] += r1[t + off]; r2[t] += r2[t + off]; }
        __syncthreads();
    }
    if (t == 0) { g_stats[b][0] = r1[0]; g_stats[b][1] = r2[0]; }
}

// ---------------- k_deint ----------------
__global__ void k_deint(const float* __restrict__ Wi, const float* __restrict__ Wj) {
    int vid = blockIdx.x * 256 + threadIdx.x;
    float4 a = ((const float4*)Wi)[vid];
    int p = vid * 2;
    g_Wi[0][p] = a.x; g_Wi[1][p] = a.y; g_Wi[0][p + 1] = a.z; g_Wi[1][p + 1] = a.w;
    float4 c = ((const float4*)Wj)[vid];
    g_Wj[0][p] = c.x; g_Wj[1][p] = c.y; g_Wj[0][p + 1] = c.z; g_Wj[1][p + 1] = c.w;
}

// ---------------- k_wd0 ----------------
__global__ void k_wd0(const float* __restrict__ wb) {
    int b = blockIdx.x >> 8;
    int seg = blockIdx.x & 255;
    int p = seg * 1024 + threadIdx.x * 4;
    float s1 = g_stats[b][0], s2 = g_stats[b][1];
    float mean = s1 * (1.f / 262144.f);
    float var = (s2 - s1 * mean) * (1.f / 262143.f);
    float istd = rsqrtf(var);
    float4 mr = *(const float4*)&g_mod[b][0][p];
    float4 mi = *(const float4*)&g_mod[b][1][p];
    float4 w01 = *(const float4*)&wb[2 * p];
    float4 w23 = *(const float4*)&wb[2 * p + 4];
    float4 orr = make_float4(
        w01.x * (1.f + (mr.x - mean) * istd),
        w01.z * (1.f + (mr.y - mean) * istd),
        w23.x * (1.f + (mr.z - mean) * istd),
        w23.z * (1.f + (mr.w - mean) * istd));
    float4 oii = make_float4(
        w01.y * (1.f + mi.x), w01.w * (1.f + mi.y),
        w23.y * (1.f + mi.z), w23.w * (1.f + mi.w));
    *(float4*)&g_wd0[b][0][p] = orr;
    *(float4*)&g_wd0[b][1][p] = oii;
}

// ---------------- complex GEMM via packed FFMA2 ----------------
// C[i,j] = sum_k A[k,i]*B[k,j] (complex). Accumulators packed along i-pairs.
// B staged into smem DUPLICATED (each scalar twice) so packed splats come
// straight from LDS.128 with zero pack-MOVs.
template<int STAGE>
__global__ __launch_bounds__(256, 2) void k_cgemm(float* __restrict__ gout) {
    constexpr int BI = 128, BJ = 64, BK = 16;
    const int b = blockIdx.z;
    const float* __restrict__ Ar; const float* __restrict__ Ai;
    const float* __restrict__ Br; const float* __restrict__ Bi;
    if (STAGE == 0) { Ar = g_Wi[0];   Ai = g_Wi[1];   Br = g_wd0[b][0]; Bi = g_wd0[b][1]; }
    else            { Ar = g_P[b][0]; Ai = g_P[b][1]; Br = g_Wj[0];     Bi = g_Wj[1]; }

    const int i0 = blockIdx.y * BI, j0 = blockIdx.x * BJ;
    __shared__ __align__(16) float Asr[BK][BI], Asi[BK][BI];
    __shared__ __align__(16) float Bsr2[BK][BJ * 2], Bsi2[BK][BJ * 2];

    u64 crp[4][4], cip[4][4];
    #pragma unroll
    for (int up = 0; up < 4; ++up)
        #pragma unroll
        for (int v = 0; v < 4; ++v) { crp[up][v] = 0ULL; cip[up][v] = 0ULL; }

    const int tid = threadIdx.x, tx = tid & 15, ty = tid >> 4;
    const int a_kk = tid >> 5, a_ii = (tid & 31) * 4;
    const int b_kk = tid >> 4, b_jj = (tid & 15) * 4;

    for (int k0 = 0; k0 < 512; k0 += BK) {
        #pragma unroll
        for (int h = 0; h < 2; ++h) {
            int kk = a_kk + h * 8;
            *(float4*)&Asr[kk][a_ii] = *(const float4*)&Ar[(k0 + kk) * 512 + i0 + a_ii];
            *(float4*)&Asi[kk][a_ii] = *(const float4*)&Ai[(k0 + kk) * 512 + i0 + a_ii];
        }
        {
            float4 vr = *(const float4*)&Br[(k0 + b_kk) * 512 + j0 + b_jj];
            float4 vi = *(const float4*)&Bi[(k0 + b_kk) * 512 + j0 + b_jj];
            *(float4*)&Bsr2[b_kk][b_jj * 2]     = make_float4(vr.x, vr.x, vr.y, vr.y);
            *(float4*)&Bsr2[b_kk][b_jj * 2 + 4] = make_float4(vr.z, vr.z, vr.w, vr.w);
            *(float4*)&Bsi2[b_kk][b_jj * 2]     = make_float4(vi.x, vi.x, vi.y, vi.y);
            *(float4*)&Bsi2[b_kk][b_jj * 2 + 4] = make_float4(vi.z, vi.z, vi.w, vi.w);
        }
        __syncthreads();
        #pragma unroll 8
        for (int kk = 0; kk < BK; ++kk) {
            // A fragments: packed i-pairs, straight from LDS.128
            ulonglong2 ar01 = *(const ulonglong2*)&Asr[kk][ty * 8];
            ulonglong2 ar23 = *(const ulonglong2*)&Asr[kk][ty * 8 + 4];
            ulonglong2 ai01 = *(const ulonglong2*)&Asi[kk][ty * 8];
            ulonglong2 ai23 = *(const ulonglong2*)&Asi[kk][ty * 8 + 4];
            u64 arp[4] = { ar01.x, ar01.y, ar23.x, ar23.y };
            u64 aip[4] = { ai01.x, ai01.y, ai23.x, ai23.y };
            u64 ainp[4] = { neg2(aip[0]), neg2(aip[1]), neg2(aip[2]), neg2(aip[3]) };
            // B fragments: packed splats, straight from duplicated smem
            ulonglong2 br01 = *(const ulonglong2*)&Bsr2[kk][tx * 8];
            ulonglong2 br23 = *(const ulonglong2*)&Bsr2[kk][tx * 8 + 4];
            ulonglong2 bi01 = *(const ulonglong2*)&Bsi2[kk][tx * 8];
            ulonglong2 bi23 = *(const ulonglong2*)&Bsi2[kk][tx * 8 + 4];
            u64 br2[4] = { br01.x, br01.y, br23.x, br23.y };
            u64 bi2[4] = { bi01.x, bi01.y, bi23.x, bi23.y };
            #pragma unroll
            for (int up = 0; up < 4; ++up)
                #pragma unroll
                for (int v = 0; v < 4; ++v) {
                    crp[up][v] = fma2(arp[up],  br2[v], crp[up][v]);
                    crp[up][v] = fma2(ainp[up], bi2[v], crp[up][v]);
                    cip[up][v] = fma2(arp[up],  bi2[v], cip[up][v]);
                    cip[up][v] = fma2(aip[up],  br2[v], cip[up][v]);
                }
        }
        __syncthreads();
    }

    // unpack to scalar microtile
    float cr[8][4], ci[8][4];
    #pragma unroll
    for (int up = 0; up < 4; ++up)
        #pragma unroll
        for (int v = 0; v < 4; ++v) {
            unpack2(crp[up][v], cr[2 * up][v], cr[2 * up + 1][v]);
            unpack2(cip[up][v], ci[2 * up][v], ci[2 * up + 1][v]);
        }

    if (STAGE == 0) {
        float* Pr = g_P[b][0]; float* Pi = g_P[b][1];
        #pragma unroll
        for (int v = 0; v < 4; ++v) {
            int j = j0 + tx * 4 + v;
            int base = j * 512 + i0 + ty * 8;
            *(float4*)&Pr[base]     = make_float4(cr[0][v], cr[1][v], cr[2][v], cr[3][v]);
            *(float4*)&Pr[base + 4] = make_float4(cr[4][v], cr[5][v], cr[6][v], cr[7][v]);
            *(float4*)&Pi[base]     = make_float4(ci[0][v], ci[1][v], ci[2][v], ci[3][v]);
            *(float4*)&Pi[base + 4] = make_float4(ci[4][v], ci[5][v], ci[6][v], ci[7][v]);
        }
    } else {
        float A_ = g_scal[0], B_ = g_scal[1], K_ = g_scal[2];
        float* O = gout + b * PL;
        #pragma unroll
        for (int u = 0; u < 8; ++u) {
            int i = i0 + ty * 8 + u;
            float4 o = make_float4(
                fmaf(ci[u][0], A_, fmaf(cr[u][0], B_, K_)),
                fmaf(ci[u][1], A_, fmaf(cr[u][1], B_, K_)),
                fmaf(ci[u][2], A_, fmaf(cr[u][2], B_, K_)),
                fmaf(ci[u][3], A_, fmaf(cr[u][3], B_, K_)));
            *(float4*)&O[i * 512 + j0 + tx * 4] = o;
        }
    }
}

// ---------------- launch ----------------
extern "C" void kernel_launch(void* const* d_in, const int* in_sizes, int n_in,
                              void* d_out, int out_size) {
    (void)in_sizes; (void)n_in; (void)out_size;
    const float* x   = (const float*)d_in[0];
    const float* Wi  = (const float*)d_in[1];
    const float* Wj  = (const float*)d_in[2];
    const float* Wb  = (const float*)d_in[3];
    const float* td  = (const float*)d_in[6];
    const float* rd  = (const float*)d_in[7];
    const float* mi  = (const float*)d_in[8];
    const float* mj  = (const float*)d_in[9];
    const float* inv = (const float*)d_in[10];
    const float* mt  = (const float*)d_in[11];
    float* out = (float*)d_out;

    k_setup<<<1, 256>>>(x, mt, td, rd);
    k_mimj<<<128, 512>>>(mi, mj, inv);
    k_mod<<<4096, 128>>>();
    k_stats<<<8, 256>>>();
    k_deint<<<512, 256>>>(Wi, Wj);
    k_wd0<<<2048, 256>>>(Wb);
    dim3 grid(8, 4, 8);
    k_cgemm<0><<<grid, 256>>>(nullptr);
    k_cgemm<1><<<grid, 256>>>(out);
}

// round 8
// speedup vs baseline: 2.4714x; 2.4612x over previous
#include <cuda_runtime.h>
#include <cuda_bf16.h>
#include <cstdint>

#define PL (512*512)
typedef unsigned long long u64;
typedef __nv_bfloat16 bf16;

// ---------------- scratch ----------------
__device__ float g_t[8][4][16][2];
__device__ float g_scal[3];
__device__ float g_part[8][512][2];
__device__ float g_stats[8][2];
__device__ float g_mi[8][2][16][512];
__device__ float g_mj[8][2][16][512];
__device__ float g_mod[8][2][PL];
__device__ bf16 g_A0[2][512 * 1024];      // Wi^T pack: [hi/lo][m'][k2 = m | 512+m]
__device__ bf16 g_B0[2][8][1024 * 1024];  // wd0 block matrix: [hi/lo][b][row][k2]
__device__ bf16 g_A1[2][8][512 * 1024];   // stage-0 output: [hi/lo][b][m'][k2' = n | 512+n]
__device__ bf16 g_B1[2][1024 * 1024];     // Wj block matrix, rows 2n' (r) / 2n'+1 (i)

#define SWZ(x) ((x) ^ (((x) >> 3) & 0x70))

__device__ __forceinline__ uint32_t smem_u32(const void* p) {
    uint32_t a;
    asm("{ .reg .u64 t; cvta.to.shared.u64 t, %1; cvt.u32.u64 %0, t; }" : "=r"(a) : "l"(p));
    return a;
}
__device__ __forceinline__ void split2(float v0, float v1, uint32_t& hi, uint32_t& lo) {
    __nv_bfloat162 h = __floats2bfloat162_rn(v0, v1);
    hi = *(uint32_t*)&h;
    float r0 = v0 - __bfloat162float(__low2bfloat16(h));
    float r1 = v1 - __bfloat162float(__high2bfloat16(h));
    __nv_bfloat162 l = __floats2bfloat162_rn(r0, r1);
    lo = *(uint32_t*)&l;
}
#define LDSM_X4(r0, r1, r2, r3, a) \
    asm volatile("ldmatrix.sync.aligned.m8n8.x4.shared.b16 {%0,%1,%2,%3}, [%4];" \
        : "=r"(r0), "=r"(r1), "=r"(r2), "=r"(r3) : "r"(a))
#define MMA16816(c, a, b) \
    asm volatile("mma.sync.aligned.m16n8k16.row.col.f32.bf16.bf16.f32 " \
        "{%0,%1,%2,%3}, {%4,%5,%6,%7}, {%8,%9}, {%0,%1,%2,%3};" \
        : "+f"((c)[0]), "+f"((c)[1]), "+f"((c)[2]), "+f"((c)[3]) \
        : "r"((a)[0]), "r"((a)[1]), "r"((a)[2]), "r"((a)[3]), "r"((b)[0]), "r"((b)[1]))
#define CP_ASYNC16(s, g) \
    asm volatile("cp.async.cg.shared.global [%0], [%1], 16;" :: "r"(s), "l"(g) : "memory")
#define CP_COMMIT()  asm volatile("cp.async.commit_group;" ::: "memory")
#define CP_WAIT(n)   asm volatile("cp.async.wait_group %0;" :: "n"(n) : "memory")

// ---------------- k_setup ----------------
__global__ void k_setup(const float* __restrict__ x, const float* __restrict__ mt,
                        const float* __restrict__ td, const float* __restrict__ rd) {
    int tid = threadIdx.x;
    for (int o = tid; o < 1024; o += 256) {
        int e = o & 1, c2 = (o >> 1) & 15, k = (o >> 5) & 3, b = o >> 7;
        float s = 0.f;
        #pragma unroll
        for (int c = 0; c < 16; ++c)
            s += x[b * 16 + c] * mt[(k * 16 + c) * 32 + c2 * 2 + e];
        g_t[b][k][c2][e] = s;
    }
    if (tid == 0) {
        float A = 0.f, Bv = 0.f, K = 0.f;
        for (int c = 0; c < 16; ++c) {
            float rr = rd[2 * c], ri = rd[2 * c + 1];
            float tr = td[2 * c], ti = td[2 * c + 1];
            A += ri; Bv -= rr; K += ti * ri - tr * rr;
        }
        g_scal[0] = A; g_scal[1] = Bv; g_scal[2] = K;
    }
}

// ---------------- k_mimj ----------------
__global__ void k_mimj(const float* __restrict__ mod_i, const float* __restrict__ mod_j,
                       const float* __restrict__ inv) {
    int b = blockIdx.x >> 4, r = blockIdx.x & 15, m = threadIdx.x;
    __shared__ float st[16][8];
    __shared__ float siv[16][2];
    if (m < 128) st[m >> 3][m & 7] = g_t[b][(m & 7) >> 1][m >> 3][m & 1];
    if (m < 32)  siv[m >> 1][m & 1] = inv[m];
    __syncthreads();

    float sir = 0.f, sii = 0.f, sjr = 0.f, sji = 0.f;
    #pragma unroll 4
    for (int c = 0; c < 16; ++c) {
        float t0r = st[c][0], t0i = st[c][1], t1r = st[c][2], t1i = st[c][3];
        float t2r = st[c][4], t2i = st[c][5], t3r = st[c][6], t3i = st[c][7];
        float ivr = siv[c][0], ivi = siv[c][1];
        float2 vi = ((const float2*)mod_i)[(c * 16 + r) * 512 + m];
        float ar = vi.x + t0r, ai = vi.y + t0i;
        float r1 = ai * t1i - ar * t1r;
        float i1 = ar * t1i + ai * t1r;
        sir += i1 * ivi - r1 * ivr;
        sii += r1 * ivi + i1 * ivr;
        float2 vj = ((const float2*)mod_j)[(c * 16 + r) * 512 + m];
        float br2 = vj.x + t2r, bi2 = vj.y + t2i;
        float r2 = bi2 * t3i - br2 * t3r;
        float i2 = br2 * t3i + bi2 * t3r;
        float idn = 1.f / (r2 * r2 + i2 * i2);
        sjr += (ivr * r2 + ivi * i2) * idn;
        sji += (ivr * i2 - ivi * r2) * idn;
    }
    g_mi[b][0][r][m] = sir; g_mi[b][1][r][m] = sii;
    g_mj[b][0][r][m] = sjr; g_mj[b][1][r][m] = sji;
}

// ---------------- k_mod ----------------
__global__ void k_mod() {
    int b = blockIdx.x >> 9, m = blockIdx.x & 511;
    int tid = threadIdx.x;
    __shared__ float smi[2][16];
    if (tid < 32) smi[tid >> 4][tid & 15] = g_mi[b][tid >> 4][tid & 15][m];
    __syncthreads();
    float s1 = 0.f, s2 = 0.f;
    #pragma unroll
    for (int q = 0; q < 4; ++q) {
        int n = tid + q * 128;
        float cr = 0.f, ci = 0.f;
        #pragma unroll
        for (int r = 0; r < 16; ++r) {
            float air = smi[0][r], aii = smi[1][r];
            float bjr = g_mj[b][0][r][n], bji = g_mj[b][1][r][n];
            cr += air * bjr - aii * bji;
            ci += air * bji + aii * bjr;
        }
        g_mod[b][0][m * 512 + n] = cr;
        g_mod[b][1][m * 512 + n] = ci;
        s1 += cr; s2 += cr * cr;
    }
    __shared__ float rs1[128], rs2[128];
    rs1[tid] = s1; rs2[tid] = s2; __syncthreads();
    for (int off = 64; off; off >>= 1) {
        if (tid < off) { rs1[tid] += rs1[tid + off]; rs2[tid] += rs2[tid + off]; }
        __syncthreads();
    }
    if (tid == 0) { g_part[b][m][0] = rs1[0]; g_part[b][m][1] = rs2[0]; }
}

// ---------------- k_stats ----------------
__global__ void k_stats() {
    int b = blockIdx.x, t = threadIdx.x;
    __shared__ float r1[256], r2[256];
    r1[t] = g_part[b][t][0] + g_part[b][t + 256][0];
    r2[t] = g_part[b][t][1] + g_part[b][t + 256][1];
    __syncthreads();
    for (int off = 128; off; off >>= 1) {
        if (t < off) { r1[t] += r1[t + off]; r2[t] += r2[t + off]; }
        __syncthreads();
    }
    if (t == 0) { g_stats[b][0] = r1[0]; g_stats[b][1] = r2[0]; }
}

// ---------------- k_packA0: Wi -> A0 = [Wir^T | Wii^T], bf16 hi/lo ----------------
__global__ void k_packA0(const float* __restrict__ Wi) {
    int mt = blockIdx.x * 32, pt = blockIdx.y * 32;
    __shared__ float sr[32][33], si[32][33];
    int t = threadIdx.x;
    #pragma unroll
    for (int rr = 0; rr < 4; ++rr) {
        int e = t + 256 * rr, ml = e >> 5, pl = e & 31;
        float2 v = ((const float2*)Wi)[(mt + ml) * 512 + pt + pl];
        sr[ml][pl] = v.x; si[ml][pl] = v.y;
    }
    __syncthreads();
    int pl = t >> 3, m4 = (t & 7) * 4;
    uint32_t hr[2], lr[2], hi_[2], li_[2];
    #pragma unroll
    for (int g = 0; g < 2; ++g) {
        split2(sr[m4 + 2 * g][pl], sr[m4 + 2 * g + 1][pl], hr[g], lr[g]);
        split2(si[m4 + 2 * g][pl], si[m4 + 2 * g + 1][pl], hi_[g], li_[g]);
    }
    size_t row = (size_t)(pt + pl) * 1024;
    int col = mt + m4;
    *(uint2*)(g_A0[0] + row + col)       = make_uint2(hr[0], hr[1]);
    *(uint2*)(g_A0[1] + row + col)       = make_uint2(lr[0], lr[1]);
    *(uint2*)(g_A0[0] + row + 512 + col) = make_uint2(hi_[0], hi_[1]);
    *(uint2*)(g_A0[1] + row + 512 + col) = make_uint2(li_[0], li_[1]);
}

// ---------------- k_packB1: Wj -> B1, rows 2n' = [Wjr | -Wji], 2n'+1 = [Wji | Wjr] ----------------
__global__ void k_packB1(const float* __restrict__ Wj) {
    int nt = blockIdx.x * 32, pt = blockIdx.y * 32;
    __shared__ float sr[32][33], si[32][33];
    int t = threadIdx.x;
    #pragma unroll
    for (int rr = 0; rr < 4; ++rr) {
        int e = t + 256 * rr, nl = e >> 5, pl = e & 31;
        float2 v = ((const float2*)Wj)[(nt + nl) * 512 + pt + pl];
        sr[nl][pl] = v.x; si[nl][pl] = v.y;
    }
    __syncthreads();
    int pl = t >> 3, m4 = (t & 7) * 4;
    uint32_t hr[2], lr[2], hi_[2], li_[2];
    #pragma unroll
    for (int g = 0; g < 2; ++g) {
        split2(sr[m4 + 2 * g][pl], sr[m4 + 2 * g + 1][pl], hr[g], lr[g]);
        split2(si[m4 + 2 * g][pl], si[m4 + 2 * g + 1][pl], hi_[g], li_[g]);
    }
    int np = pt + pl;
    size_t row_r = (size_t)(2 * np) * 1024;
    size_t row_i = (size_t)(2 * np + 1) * 1024;
    int col = nt + m4;
    *(uint2*)(g_B1[0] + row_r + col)       = make_uint2(hr[0], hr[1]);
    *(uint2*)(g_B1[1] + row_r + col)       = make_uint2(lr[0], lr[1]);
    *(uint2*)(g_B1[0] + row_r + 512 + col) = make_uint2(hi_[0] ^ 0x80008000u, hi_[1] ^ 0x80008000u);
    *(uint2*)(g_B1[1] + row_r + 512 + col) = make_uint2(li_[0] ^ 0x80008000u, li_[1] ^ 0x80008000u);
    *(uint2*)(g_B1[0] + row_i + col)       = make_uint2(hi_[0], hi_[1]);
    *(uint2*)(g_B1[1] + row_i + col)       = make_uint2(li_[0], li_[1]);
    *(uint2*)(g_B1[0] + row_i + 512 + col) = make_uint2(hr[0], hr[1]);
    *(uint2*)(g_B1[1] + row_i + 512 + col) = make_uint2(lr[0], lr[1]);
}

// ---------------- k_packB0: wd0 -> B0 block matrix per batch ----------------
__global__ void k_packB0(const float* __restrict__ wb) {
    int mt = blockIdx.x * 32, nt = blockIdx.y * 32, b = blockIdx.z;
    float s1 = g_stats[b][0], s2 = g_stats[b][1];
    float mean = s1 * (1.f / 262144.f);
    float var = (s2 - s1 * mean) * (1.f / 262143.f);
    float istd = rsqrtf(var);
    __shared__ float wr[32][33], wi[32][33];
    int t = threadIdx.x;
    #pragma unroll
    for (int rr = 0; rr < 4; ++rr) {
        int e = t + 256 * rr, ml = e >> 5, nl = e & 31;
        int idx = (mt + ml) * 512 + nt + nl;
        float2 w = ((const float2*)wb)[idx];
        wr[ml][nl] = w.x * (1.f + (g_mod[b][0][idx] - mean) * istd);
        wi[ml][nl] = w.y * (1.f + g_mod[b][1][idx]);
    }
    __syncthreads();
    int nl = t >> 3, m4 = (t & 7) * 4;
    uint32_t hr[2], lr[2], hi_[2], li_[2];
    #pragma unroll
    for (int g = 0; g < 2; ++g) {
        split2(wr[m4 + 2 * g][nl], wr[m4 + 2 * g + 1][nl], hr[g], lr[g]);
        split2(wi[m4 + 2 * g][nl], wi[m4 + 2 * g + 1][nl], hi_[g], li_[g]);
    }
    size_t row_r = (size_t)(nt + nl) * 1024;
    size_t row_i = (size_t)(512 + nt + nl) * 1024;
    int col = mt + m4;
    bf16* Bh = g_B0[0][b]; bf16* Bl = g_B0[1][b];
    *(uint2*)(Bh + row_r + col)       = make_uint2(hr[0], hr[1]);
    *(uint2*)(Bl + row_r + col)       = make_uint2(lr[0], lr[1]);
    *(uint2*)(Bh + row_r + 512 + col) = make_uint2(hi_[0] ^ 0x80008000u, hi_[1] ^ 0x80008000u);
    *(uint2*)(Bl + row_r + 512 + col) = make_uint2(li_[0] ^ 0x80008000u, li_[1] ^ 0x80008000u);
    *(uint2*)(Bh + row_i + col)       = make_uint2(hi_[0], hi_[1]);
    *(uint2*)(Bl + row_i + col)       = make_uint2(li_[0], li_[1]);
    *(uint2*)(Bh + row_i + 512 + col) = make_uint2(hr[0], hr[1]);
    *(uint2*)(Bl + row_i + 512 + col) = make_uint2(lr[0], lr[1]);
}

// ---------------- mma.sync GEMM ----------------
// smem buffer layout (per 64KB buffer): Ahi @0, Alo @16K, Bhi @32K, Blo @48K.
// Each tile: 128 rows x 64 k (bf16) = 128B rows, SW128 swizzled.
__device__ __forceinline__ void prefetch_chunk(
    const bf16* __restrict__ Ah, const bf16* __restrict__ Al,
    const bf16* __restrict__ Bh, const bf16* __restrict__ Bl,
    int arow, int brow, int kb, uint32_t sdst, int tid) {
    const bf16* srcs[4] = { Ah, Al, Bh, Bl };
    const int rows0[4] = { arow, arow, brow, brow };
    #pragma unroll
    for (int arr = 0; arr < 4; ++arr) {
        #pragma unroll
        for (int i = 0; i < 4; ++i) {
            int u = tid + 256 * i, row = u >> 3, seg = u & 7;
            const bf16* g = srcs[arr] + (size_t)(rows0[arr] + row) * 1024 + kb + seg * 8;
            uint32_t s = sdst + arr * 16384 + SWZ(row * 128 + seg * 16);
            CP_ASYNC16(s, g);
        }
    }
    CP_COMMIT();
}

template<int STAGE>
__global__ void __launch_bounds__(256, 1) k_mma(float* __restrict__ gout) {
    extern __shared__ __align__(1024) char smem[];
    const int tid = threadIdx.x, wid = tid >> 5, lane = tid & 31;
    const int wm = wid >> 1, wn = wid & 1;
    const int b = blockIdx.z, My = blockIdx.y, Nx = blockIdx.x;
    const bf16 *Ahi, *Alo, *Bhi, *Blo;
    if (STAGE == 0) { Ahi = g_A0[0];    Alo = g_A0[1];    Bhi = g_B0[0][b]; Blo = g_B0[1][b]; }
    else            { Ahi = g_A1[0][b]; Alo = g_A1[1][b]; Bhi = g_B1[0];    Blo = g_B1[1]; }
    const int arow = My * 128, brow = Nx * 128;
    const uint32_t sb = smem_u32(smem);

    float c[2][8][4];
    #pragma unroll
    for (int mt = 0; mt < 2; ++mt)
        #pragma unroll
        for (int nt = 0; nt < 8; ++nt)
            #pragma unroll
            for (int q = 0; q < 4; ++q) c[mt][nt][q] = 0.f;

    prefetch_chunk(Ahi, Alo, Bhi, Blo, arow, brow, 0, sb, tid);

    for (int ch = 0; ch < 16; ++ch) {
        const uint32_t sbuf = sb + (ch & 1) * 65536;
        if (ch + 1 < 16) {
            prefetch_chunk(Ahi, Alo, Bhi, Blo, arow, brow, (ch + 1) * 64,
                           sb + ((ch + 1) & 1) * 65536, tid);
            CP_WAIT(1);
        } else {
            CP_WAIT(0);
        }
        __syncthreads();

        const uint32_t sA = sbuf, sAl = sbuf + 16384, sB = sbuf + 32768, sBl = sbuf + 49152;
        #pragma unroll
        for (int ks = 0; ks < 4; ++ks) {
            uint32_t ah[2][4], al[2][4], bh[8][2], bl[8][2];
            #pragma unroll
            for (int mt = 0; mt < 2; ++mt) {
                int row = wm * 32 + mt * 16 + (lane & 15);
                uint32_t off = SWZ(row * 128 + ks * 32 + (lane >> 4) * 16);
                LDSM_X4(ah[mt][0], ah[mt][1], ah[mt][2], ah[mt][3], sA + off);
                LDSM_X4(al[mt][0], al[mt][1], al[mt][2], al[mt][3], sAl + off);
            }
            #pragma unroll
            for (int ntp = 0; ntp < 4; ++ntp) {
                int row = wn * 64 + ntp * 16 + (lane >> 4) * 8 + (lane & 7);
                uint32_t off = SWZ(row * 128 + ks * 32 + ((lane >> 3) & 1) * 16);
                LDSM_X4(bh[2 * ntp][0], bh[2 * ntp][1], bh[2 * ntp + 1][0], bh[2 * ntp + 1][1], sB + off);
                LDSM_X4(bl[2 * ntp][0], bl[2 * ntp][1], bl[2 * ntp + 1][0], bl[2 * ntp + 1][1], sBl + off);
            }
            #pragma unroll
            for (int mt = 0; mt < 2; ++mt)
                #pragma unroll
                for (int nt = 0; nt < 8; ++nt) {
                    MMA16816(c[mt][nt], ah[mt], bh[nt]);
                    MMA16816(c[mt][nt], al[mt], bh[nt]);
                    MMA16816(c[mt][nt], ah[mt], bl[nt]);
                }
        }
        __syncthreads();
    }

    // ---------------- epilogue ----------------
    const int r0 = My * 128 + wm * 32 + (lane >> 2);
    if (STAGE == 0) {
        bf16* dh = g_A1[0][b]; bf16* dl = g_A1[1][b];
        #pragma unroll
        for (int mt = 0; mt < 2; ++mt)
            #pragma unroll
            for (int nt = 0; nt < 8; ++nt) {
                int row = r0 + mt * 16;
                int col = Nx * 128 + wn * 64 + nt * 8 + 2 * (lane & 3);
                uint32_t h, l;
                split2(c[mt][nt][0], c[mt][nt][1], h, l);
                *(uint32_t*)(dh + (size_t)row * 1024 + col) = h;
                *(uint32_t*)(dl + (size_t)row * 1024 + col) = l;
                split2(c[mt][nt][2], c[mt][nt][3], h, l);
                *(uint32_t*)(dh + (size_t)(row + 8) * 1024 + col) = h;
                *(uint32_t*)(dl + (size_t)(row + 8) * 1024 + col) = l;
            }
    } else {
        const float A_ = g_scal[0], B_ = g_scal[1], K_ = g_scal[2];
        float* O = gout + b * PL;
        #pragma unroll
        for (int mt = 0; mt < 2; ++mt)
            #pragma unroll
            for (int nt = 0; nt < 8; ++nt) {
                int row = r0 + mt * 16;
                int np = Nx * 64 + wn * 32 + nt * 4 + (lane & 3);
                O[(size_t)row * 512 + np] =
                    fmaf(c[mt][nt][1], A_, fmaf(c[mt][nt][0], B_, K_));
                O[(size_t)(row + 8) * 512 + np] =
                    fmaf(c[mt][nt][3], A_, fmaf(c[mt][nt][2], B_, K_));
            }
    }
}

// ---------------- launch ----------------
extern "C" void kernel_launch(void* const* d_in, const int* in_sizes, int n_in,
                              void* d_out, int out_size) {
    (void)in_sizes; (void)n_in; (void)out_size;
    const float* x   = (const float*)d_in[0];
    const float* Wi  = (const float*)d_in[1];
    const float* Wj  = (const float*)d_in[2];
    const float* Wb  = (const float*)d_in[3];
    const float* td  = (const float*)d_in[6];
    const float* rd  = (const float*)d_in[7];
    const float* mi  = (const float*)d_in[8];
    const float* mj  = (const float*)d_in[9];
    const float* inv = (const float*)d_in[10];
    const float* mt  = (const float*)d_in[11];
    float* out = (float*)d_out;

    const int SMEM_SZ = 2 * 65536;   // 128 KB
    cudaFuncSetAttribute(k_mma<0>, cudaFuncAttributeMaxDynamicSharedMemorySize, SMEM_SZ);
    cudaFuncSetAttribute(k_mma<1>, cudaFuncAttributeMaxDynamicSharedMemorySize, SMEM_SZ);

    k_setup<<<1, 256>>>(x, mt, td, rd);
    k_mimj<<<128, 512>>>(mi, mj, inv);
    k_mod<<<4096, 128>>>();
    k_stats<<<8, 256>>>();
    k_packA0<<<dim3(16, 16), 256>>>(Wi);
    k_packB1<<<dim3(16, 16), 256>>>(Wj);
    k_packB0<<<dim3(16, 16, 8), 256>>>(Wb);
    dim3 grid(8, 4, 8);
    k_mma<0><<<grid, 256, SMEM_SZ>>>(nullptr);
    k_mma<1><<<grid, 256, SMEM_SZ>>>(out);
}